// round 5
// baseline (speedup 1.0000x reference)
#include <cuda_runtime.h>
#include <cstdint>
#include <cstdio>

// ---------------- problem constants ----------------
constexpr int NN  = 50000;   // nodes
constexpr int NE  = 800000;  // edges
constexpr int DD  = 128;     // channels
constexpr int NH  = 8;       // heads
constexpr int EDD = 32;      // edge_dim
constexpr int HD  = 512;     // mlp hidden
constexpr int GG  = 64;      // graphs
constexpr float NEG  = 0.2f;
constexpr float EPSC = 1e-5f;

#define NEG_INF (__int_as_float(0xff800000u))

// ---------------- device scratch (no allocs allowed) ----------------
__device__ float g_xl  [NN * DD];
__device__ float g_xr  [NN * DD];
__device__ float g_xres[NN * DD];
__device__ float g_xtmp[NN * DD];
__device__ float g_x2  [NN * DD];
__device__ float g_xcur[NN * DD];
__device__ float g_h   [(size_t)NN * HD];        // 102 MB
__device__ float g_alpha[(size_t)NE * NH];       // CSR-ordered: [pos][head], 25.6 MB

__device__ int g_deg   [NN];
__device__ int g_rowptr[NN + 1];
__device__ int g_wp    [NN];
__device__ int g_pos   [NE];   // edge id -> CSR position
__device__ int g_src   [NE];   // CSR position -> src node
__device__ int g_gcnt  [GG];

__device__ float g_bnstat[2 * HD];
__device__ float g_bns[HD];
__device__ float g_bnt[HD];
__device__ float g_gstat[2 * GG];
__device__ float g_gmean[GG];
__device__ float g_ginv [GG];

// ---------------- setup kernels ----------------
__global__ void zero_init_kernel() {
    int i = blockIdx.x * blockDim.x + threadIdx.x;
    if (i < NN) g_deg[i] = 0;
    if (i < GG) g_gcnt[i] = 0;
}

__global__ void hist_kernel(const int* __restrict__ ei, const int* __restrict__ nb) {
    int i = blockIdx.x * blockDim.x + threadIdx.x;
    if (i < NE) atomicAdd(&g_deg[ei[NE + i]], 1);   // dst
    if (i < NN) atomicAdd(&g_gcnt[nb[i]], 1);
}

__global__ void scan_kernel() {
    __shared__ int part[1024];
    constexpr int CHUNK = (NN + 1023) / 1024;  // 49
    int t = threadIdx.x;
    int base = t * CHUNK;
    int s = 0;
    for (int i = 0; i < CHUNK; i++) {
        int idx = base + i;
        if (idx < NN) s += g_deg[idx];
    }
    part[t] = s;
    __syncthreads();
    for (int off = 1; off < 1024; off <<= 1) {
        int v = (t >= off) ? part[t - off] : 0;
        __syncthreads();
        part[t] += v;
        __syncthreads();
    }
    int run = (t == 0) ? 0 : part[t - 1];
    for (int i = 0; i < CHUNK; i++) {
        int idx = base + i;
        if (idx < NN) {
            g_rowptr[idx] = run;
            g_wp[idx] = run;
            run += g_deg[idx];
        }
    }
    if (t == 1023) g_rowptr[NN] = part[1023];
}

__global__ void scatter_kernel(const int* __restrict__ ei) {
    int e = blockIdx.x * blockDim.x + threadIdx.x;
    if (e >= NE) return;
    int s = ei[e];
    int d = ei[NE + e];
    int p = atomicAdd(&g_wp[d], 1);
    g_pos[e] = p;
    g_src[p] = s;
}

__global__ void zero_stats_kernel() {
    int i = blockIdx.x * blockDim.x + threadIdx.x;
    if (i < 2 * HD) g_bnstat[i] = 0.f;
    if (i < 2 * GG) g_gstat[i] = 0.f;
}

// ---------------- generic fp32 GEMM: C[N,M] = op_A(A[N,K]) @ W[K,M] (+bias)(+add) ----------------
__global__ __launch_bounds__(256)
void gemm_kernel(const float* __restrict__ A, const float* __restrict__ W,
                 const float* __restrict__ bias, const float* __restrict__ add,
                 const float* __restrict__ tS, const float* __restrict__ tT,
                 float* __restrict__ C, int N, int K, int M) {
    constexpr int BM = 128, BN = 64, BK = 16;
    __shared__ float As[BK][BM];
    __shared__ float Ws[BK][BN];

    int tid = threadIdx.x;
    int ty = tid >> 4, tx = tid & 15;
    int rowBase = blockIdx.x * BM;
    int colBase = blockIdx.y * BN;

    float acc[8][4];
#pragma unroll
    for (int i = 0; i < 8; i++)
#pragma unroll
        for (int j = 0; j < 4; j++) acc[i][j] = 0.f;

    for (int k0 = 0; k0 < K; k0 += BK) {
#pragma unroll
        for (int q = 0; q < 2; q++) {
            int f  = tid * 2 + q;
            int r  = f >> 2;
            int qq = f & 3;
            int grow = rowBase + r;
            int gk   = k0 + qq * 4;
            float4 v = make_float4(0.f, 0.f, 0.f, 0.f);
            if (grow < N) {
                v = *(const float4*)&A[(size_t)grow * K + gk];
                if (tS) {
                    float4 sv = *(const float4*)&tS[gk];
                    float4 tv = *(const float4*)&tT[gk];
                    v.x = fmaxf(fmaf(v.x, sv.x, tv.x), 0.f);
                    v.y = fmaxf(fmaf(v.y, sv.y, tv.y), 0.f);
                    v.z = fmaxf(fmaf(v.z, sv.z, tv.z), 0.f);
                    v.w = fmaxf(fmaf(v.w, sv.w, tv.w), 0.f);
                }
            }
            As[qq * 4 + 0][r] = v.x;
            As[qq * 4 + 1][r] = v.y;
            As[qq * 4 + 2][r] = v.z;
            As[qq * 4 + 3][r] = v.w;
        }
        {
            int k = tid >> 4;
            int c = (tid & 15) * 4;
            float4 wv = *(const float4*)&W[(size_t)(k0 + k) * M + colBase + c];
            *(float4*)&Ws[k][c] = wv;
        }
        __syncthreads();

#pragma unroll
        for (int kk = 0; kk < BK; kk++) {
            float4 a0 = *(float4*)&As[kk][ty * 8];
            float4 a1 = *(float4*)&As[kk][ty * 8 + 4];
            float4 w  = *(float4*)&Ws[kk][tx * 4];
            float av[8] = {a0.x, a0.y, a0.z, a0.w, a1.x, a1.y, a1.z, a1.w};
            float wv[4] = {w.x, w.y, w.z, w.w};
#pragma unroll
            for (int i = 0; i < 8; i++)
#pragma unroll
                for (int j = 0; j < 4; j++)
                    acc[i][j] = fmaf(av[i], wv[j], acc[i][j]);
        }
        __syncthreads();
    }

    int colb = colBase + tx * 4;
    float4 bv = make_float4(0.f, 0.f, 0.f, 0.f);
    if (bias) bv = *(const float4*)&bias[colb];
#pragma unroll
    for (int i = 0; i < 8; i++) {
        int grow = rowBase + ty * 8 + i;
        if (grow >= N) break;
        float4 o = make_float4(acc[i][0] + bv.x, acc[i][1] + bv.y,
                               acc[i][2] + bv.z, acc[i][3] + bv.w);
        if (add) {
            float4 av = *(const float4*)&add[(size_t)grow * M + colb];
            o.x += av.x; o.y += av.y; o.z += av.z; o.w += av.w;
        }
        *(float4*)&C[(size_t)grow * M + colb] = o;
    }
}

// ---------------- fused edge kernel: e-projection GEMM + leaky + att dot ----------------
// Block = 256 threads (8 warps), 128 edges/block (16 per warp). NE % 128 == 0.
// alpha written in CSR order at g_pos[e].
__device__ __forceinline__ float lky(float v) { return v > 0.f ? v : NEG * v; }

__global__ __launch_bounds__(256)
void edge_fused_kernel(const int* __restrict__ ei, const float* __restrict__ ea,
                       const float* __restrict__ We, const float* __restrict__ att) {
    constexpr int TE = 128;   // edges per block
    constexpr int EW = 16;    // edges per warp
    __shared__ float ea_s[TE * EDD];      // 16 KB
    __shared__ float We_s[EDD * DD];      // 16 KB
    __shared__ float att_s[DD];

    int tid  = threadIdx.x;
    int lane = tid & 31;
    int w    = tid >> 5;
    int e0   = blockIdx.x * TE;

    // stage We (32x128) and this block's edge_attr tile (128x32), both coalesced
    {
        const float4* We4 = (const float4*)We;
        float4* Ws4 = (float4*)We_s;
#pragma unroll
        for (int i = 0; i < 4; i++) Ws4[tid + 256 * i] = We4[tid + 256 * i];
        const float4* ea4 = (const float4*)(ea + (size_t)e0 * EDD);
        float4* es4 = (float4*)ea_s;
#pragma unroll
        for (int i = 0; i < 4; i++) es4[tid + 256 * i] = ea4[tid + 256 * i];
        if (tid < DD) att_s[tid] = att[tid];
    }
    __syncthreads();

    // GEMM phase: acc[i][0..3] = e-projection channels [lane*4 .. lane*4+3] of edge (w*EW+i)
    float acc[EW][4];
#pragma unroll
    for (int i = 0; i < EW; i++)
#pragma unroll
        for (int j = 0; j < 4; j++) acc[i][j] = 0.f;

#pragma unroll
    for (int k = 0; k < EDD; k++) {
        float4 wv = *(float4*)&We_s[k * DD + lane * 4];
#pragma unroll
        for (int i = 0; i < EW; i++) {
            float a = ea_s[(w * EW + i) * EDD + k];   // warp-broadcast LDS
            acc[i][0] = fmaf(a, wv.x, acc[i][0]);
            acc[i][1] = fmaf(a, wv.y, acc[i][1]);
            acc[i][2] = fmaf(a, wv.z, acc[i][2]);
            acc[i][3] = fmaf(a, wv.w, acc[i][3]);
        }
    }

    float4 attv = *(float4*)&att_s[lane * 4];

    // alpha phase: gather xl[src], xr[dst], leaky, dot, head-reduce, scatter to CSR pos
#pragma unroll 4
    for (int i = 0; i < EW; i++) {
        int e = e0 + w * EW + i;
        int s = ei[e];
        int d = ei[NE + e];
        float4 xlv = *(const float4*)&g_xl[(size_t)s * DD + lane * 4];
        float4 xrv = *(const float4*)&g_xr[(size_t)d * DD + lane * 4];
        float mx = lky(acc[i][0] + xlv.x + xrv.x);
        float my = lky(acc[i][1] + xlv.y + xrv.y);
        float mz = lky(acc[i][2] + xlv.z + xrv.z);
        float mw = lky(acc[i][3] + xlv.w + xrv.w);
        float p = mx * attv.x + my * attv.y + mz * attv.z + mw * attv.w;
        p += __shfl_xor_sync(0xffffffffu, p, 1);
        p += __shfl_xor_sync(0xffffffffu, p, 2);
        int pos = g_pos[e];
        if ((lane & 3) == 0) g_alpha[(size_t)pos * NH + (lane >> 2)] = p;
    }
}

// ---------------- node aggregation: online softmax, CSR-sequential streams ----------------
__global__ __launch_bounds__(256)
void node_agg_kernel() {
    int lane = threadIdx.x & 31;
    int n = blockIdx.x * 8 + (threadIdx.x >> 5);
    if (n >= NN) return;
    int h = lane >> 2;
    int beg = g_rowptr[n], end = g_rowptr[n + 1];
    float m = NEG_INF, den = 0.f;
    float4 acc = make_float4(0.f, 0.f, 0.f, 0.f);

    int j = beg;
    for (; j + 1 < end; j += 2) {
        // issue both iterations' loads up front (independent), then two dependent updates
        float a0 = g_alpha[(size_t)j * NH + h];
        float a1 = g_alpha[(size_t)(j + 1) * NH + h];
        int   s0 = g_src[j];
        int   s1 = g_src[j + 1];
        float4 x0 = *(const float4*)&g_xl[(size_t)s0 * DD + lane * 4];
        float4 x1 = *(const float4*)&g_xl[(size_t)s1 * DD + lane * 4];

        float mn = fmaxf(m, a0);
        float corr = __expf(m - mn);
        float p = __expf(a0 - mn);
        den = den * corr + p;
        acc.x = acc.x * corr + p * x0.x;
        acc.y = acc.y * corr + p * x0.y;
        acc.z = acc.z * corr + p * x0.z;
        acc.w = acc.w * corr + p * x0.w;
        m = mn;

        mn = fmaxf(m, a1);
        corr = __expf(m - mn);
        p = __expf(a1 - mn);
        den = den * corr + p;
        acc.x = acc.x * corr + p * x1.x;
        acc.y = acc.y * corr + p * x1.y;
        acc.z = acc.z * corr + p * x1.z;
        acc.w = acc.w * corr + p * x1.w;
        m = mn;
    }
    for (; j < end; j++) {
        float a = g_alpha[(size_t)j * NH + h];
        int s = g_src[j];
        float4 xlv = *(const float4*)&g_xl[(size_t)s * DD + lane * 4];
        float mn = fmaxf(m, a);
        float corr = __expf(m - mn);
        float p = __expf(a - mn);
        den = den * corr + p;
        acc.x = acc.x * corr + p * xlv.x;
        acc.y = acc.y * corr + p * xlv.y;
        acc.z = acc.z * corr + p * xlv.z;
        acc.w = acc.w * corr + p * xlv.w;
        m = mn;
    }

    float inv = 1.f / (den + 1e-16f);
    float4 rv = *(const float4*)&g_xres[(size_t)n * DD + lane * 4];
    float4 o = make_float4(acc.x * inv + rv.x, acc.y * inv + rv.y,
                           acc.z * inv + rv.z, acc.w * inv + rv.w);
    *(float4*)&g_xtmp[(size_t)n * DD + lane * 4] = o;
}

// ---------------- BN column stats over g_h [NN, HD] ----------------
__global__ void colstats_kernel() {
    int col = blockIdx.x * 128 + threadIdx.x;
    constexpr int CHUNK = (NN + 63) / 64;  // 782
    int r0 = blockIdx.y * CHUNK;
    int r1 = min(r0 + CHUNK, NN);
    float s = 0.f, q = 0.f;
    for (int r = r0; r < r1; r++) {
        float v = g_h[(size_t)r * HD + col];
        s += v;
        q += v * v;
    }
    atomicAdd(&g_bnstat[col], s);
    atomicAdd(&g_bnstat[HD + col], q);
}

__global__ void bn_final_kernel(const float* __restrict__ gamma, const float* __restrict__ beta) {
    int c = threadIdx.x;
    if (c >= HD) return;
    float invn = 1.f / (float)NN;
    float mu  = g_bnstat[c] * invn;
    float var = g_bnstat[HD + c] * invn - mu * mu;
    float istd = rsqrtf(var + EPSC);
    float s = gamma[c] * istd;
    g_bns[c] = s;
    g_bnt[c] = beta[c] - mu * s;
}

// ---------------- graph LayerNorm stats over g_x2 ----------------
__global__ __launch_bounds__(256)
void ln_stats_kernel(const int* __restrict__ nb) {
    int lane = threadIdx.x & 31;
    int n = blockIdx.x * 8 + (threadIdx.x >> 5);
    if (n >= NN) return;
    float4 v = *(const float4*)&g_x2[(size_t)n * DD + lane * 4];
    float s = v.x + v.y + v.z + v.w;
    float q = v.x * v.x + v.y * v.y + v.z * v.z + v.w * v.w;
#pragma unroll
    for (int off = 16; off > 0; off >>= 1) {
        s += __shfl_xor_sync(0xffffffffu, s, off);
        q += __shfl_xor_sync(0xffffffffu, q, off);
    }
    if (lane == 0) {
        int g = nb[n];
        atomicAdd(&g_gstat[g], s);
        atomicAdd(&g_gstat[GG + g], q);
    }
}

__global__ void ln_final_kernel() {
    int g = threadIdx.x;
    if (g >= GG) return;
    float cnt = fmaxf((float)g_gcnt[g], 1.f);
    float denom = cnt * (float)DD;
    float mean = g_gstat[g] / denom;
    float var  = g_gstat[GG + g] / denom - mean * mean;
    g_gmean[g] = mean;
    g_ginv[g]  = rsqrtf(var + EPSC);
}

__global__ void ln_apply_kernel(const int* __restrict__ nb,
                                const float* __restrict__ gamma,
                                const float* __restrict__ beta,
                                float* __restrict__ dst) {
    int idx = blockIdx.x * blockDim.x + threadIdx.x;  // float4 granularity
    if (idx >= NN * (DD / 4)) return;
    int n  = idx >> 5;
    int c4 = (idx & 31) * 4;
    int g  = nb[n];
    float mean = g_gmean[g];
    float ginv = g_ginv[g];
    float4 v  = *(const float4*)&g_x2[(size_t)n * DD + c4];
    float4 ga = *(const float4*)&gamma[c4];
    float4 be = *(const float4*)&beta[c4];
    float4 o;
    o.x = (v.x - mean) * ginv * ga.x + be.x;
    o.y = (v.y - mean) * ginv * ga.y + be.y;
    o.z = (v.z - mean) * ginv * ga.z + be.z;
    o.w = (v.w - mean) * ginv * ga.w + be.w;
    *(float4*)&dst[(size_t)n * DD + c4] = o;
}

// ---------------- host launch ----------------
extern "C" void kernel_launch(void* const* d_in, const int* in_sizes, int n_in,
                              void* d_out, int out_size) {
    const float* x    = (const float*)d_in[0];
    const int*   nb   = (const int*)  d_in[1];
    const int*   ei   = (const int*)  d_in[2];
    const float* ea   = (const float*)d_in[3];
    const float* Wl   = (const float*)d_in[4];
    const float* bl   = (const float*)d_in[5];
    const float* Wr   = (const float*)d_in[6];
    const float* br   = (const float*)d_in[7];
    const float* We   = (const float*)d_in[8];
    const float* att  = (const float*)d_in[9];
    const float* bias = (const float*)d_in[10];
    const float* Wres = (const float*)d_in[11];
    const float* W1   = (const float*)d_in[12];
    const float* b1   = (const float*)d_in[13];
    const float* bng  = (const float*)d_in[14];
    const float* bnb  = (const float*)d_in[15];
    const float* W2   = (const float*)d_in[16];
    const float* b2   = (const float*)d_in[17];
    const float* lng  = (const float*)d_in[18];
    const float* lnb  = (const float*)d_in[19];
    float* out = (float*)d_out;

    void* p;
    cudaGetSymbolAddress(&p, g_xl);   float* pxl   = (float*)p;
    cudaGetSymbolAddress(&p, g_xr);   float* pxr   = (float*)p;
    cudaGetSymbolAddress(&p, g_xres); float* pxres = (float*)p;
    cudaGetSymbolAddress(&p, g_xtmp); float* pxtmp = (float*)p;
    cudaGetSymbolAddress(&p, g_x2);   float* px2   = (float*)p;
    cudaGetSymbolAddress(&p, g_xcur); float* pxcur = (float*)p;
    cudaGetSymbolAddress(&p, g_h);    float* ph    = (float*)p;
    cudaGetSymbolAddress(&p, g_bns);  float* pbns  = (float*)p;
    cudaGetSymbolAddress(&p, g_bnt);  float* pbnt  = (float*)p;

    // CSR build + graph counts (shared by both layers)
    zero_init_kernel<<<(NN + 255) / 256, 256>>>();
    hist_kernel<<<(NE + 255) / 256, 256>>>(ei, nb);
    scan_kernel<<<1, 1024>>>();
    scatter_kernel<<<(NE + 255) / 256, 256>>>(ei);

    const int GR = (NN + 127) / 128;   // 391

    const float* xin = x;
    for (int l = 0; l < 2; l++) {
        zero_stats_kernel<<<2, 1024>>>();

        gemm_kernel<<<dim3(GR, 2), 256>>>(xin, Wl + (size_t)l * DD * DD, bl + l * DD,
                                          nullptr, nullptr, nullptr, pxl, NN, DD, DD);
        gemm_kernel<<<dim3(GR, 2), 256>>>(xin, Wr + (size_t)l * DD * DD, br + l * DD,
                                          nullptr, nullptr, nullptr, pxr, NN, DD, DD);
        gemm_kernel<<<dim3(GR, 2), 256>>>(xin, Wres + (size_t)l * DD * DD, bias + l * DD,
                                          nullptr, nullptr, nullptr, pxres, NN, DD, DD);

        edge_fused_kernel<<<NE / 128, 256>>>(ei, ea, We + (size_t)l * EDD * DD, att + l * DD);
        node_agg_kernel<<<(NN + 7) / 8, 256>>>();

        gemm_kernel<<<dim3(GR, 8), 256>>>(pxtmp, W1 + (size_t)l * DD * HD, b1 + l * HD,
                                          nullptr, nullptr, nullptr, ph, NN, DD, HD);
        colstats_kernel<<<dim3(4, 64), 128>>>();
        bn_final_kernel<<<1, 512>>>(bng + l * HD, bnb + l * HD);
        gemm_kernel<<<dim3(GR, 2), 256>>>(ph, W2 + (size_t)l * HD * DD, b2 + l * DD,
                                          pxtmp, pbns, pbnt, px2, NN, HD, DD);

        ln_stats_kernel<<<(NN + 7) / 8, 256>>>(nb);
        ln_final_kernel<<<1, 64>>>();
        float* dst = (l == 1) ? out : pxcur;
        ln_apply_kernel<<<(NN * (DD / 4) + 255) / 256, 256>>>(nb, lng + l * DD, lnb + l * DD, dst);

        xin = pxcur;
    }
}

// round 7
// speedup vs baseline: 1.1660x; 1.1660x over previous
#include <cuda_runtime.h>
#include <cstdint>
#include <cstdio>

// ---------------- problem constants ----------------
constexpr int NN  = 50000;   // nodes
constexpr int NE  = 800000;  // edges
constexpr int DD  = 128;     // channels
constexpr int NH  = 8;       // heads
constexpr int EDD = 32;      // edge_dim
constexpr int HD  = 512;     // mlp hidden
constexpr int GG  = 64;      // graphs
constexpr float NEG  = 0.2f;
constexpr float EPSC = 1e-5f;

#define NEG_INF (__int_as_float(0xff800000u))

// ---------------- device scratch (no allocs allowed) ----------------
__device__ float g_xl  [NN * DD];
__device__ float g_xr  [NN * DD];
__device__ float g_xres[NN * DD];
__device__ float g_xtmp[NN * DD];
__device__ float g_x2  [NN * DD];
__device__ float g_xcur[NN * DD];
__device__ float g_h   [(size_t)NN * HD];        // 102 MB
__device__ float g_alpha[(size_t)NE * NH];       // CSR-ordered: [pos][head]

__device__ int g_deg   [NN];
__device__ int g_rowptr[NN + 1];
__device__ int g_wp    [NN];
__device__ int g_pos   [NE];   // edge id -> CSR position
__device__ int g_src   [NE];   // CSR position -> src node
__device__ int g_gcnt  [GG];

__device__ float g_bnstat[2 * HD];
__device__ float g_bns[HD];
__device__ float g_bnt[HD];
__device__ float g_gstat[2 * GG];
__device__ float g_gmean[GG];
__device__ float g_ginv [GG];

// ---------------- setup kernels ----------------
__global__ void zero_init_kernel() {
    int i = blockIdx.x * blockDim.x + threadIdx.x;
    if (i < NN) g_deg[i] = 0;
    if (i < GG) g_gcnt[i] = 0;
}

__global__ void hist_kernel(const int* __restrict__ ei, const int* __restrict__ nb) {
    int i = blockIdx.x * blockDim.x + threadIdx.x;
    if (i < NE) atomicAdd(&g_deg[ei[NE + i]], 1);   // dst
    if (i < NN) atomicAdd(&g_gcnt[nb[i]], 1);
}

__global__ void scan_kernel() {
    __shared__ int part[1024];
    constexpr int CHUNK = (NN + 1023) / 1024;  // 49
    int t = threadIdx.x;
    int base = t * CHUNK;
    int s = 0;
    for (int i = 0; i < CHUNK; i++) {
        int idx = base + i;
        if (idx < NN) s += g_deg[idx];
    }
    part[t] = s;
    __syncthreads();
    for (int off = 1; off < 1024; off <<= 1) {
        int v = (t >= off) ? part[t - off] : 0;
        __syncthreads();
        part[t] += v;
        __syncthreads();
    }
    int run = (t == 0) ? 0 : part[t - 1];
    for (int i = 0; i < CHUNK; i++) {
        int idx = base + i;
        if (idx < NN) {
            g_rowptr[idx] = run;
            g_wp[idx] = run;
            run += g_deg[idx];
        }
    }
    if (t == 1023) g_rowptr[NN] = part[1023];
}

__global__ void scatter_kernel(const int* __restrict__ ei) {
    int e = blockIdx.x * blockDim.x + threadIdx.x;
    if (e >= NE) return;
    int s = ei[e];
    int d = ei[NE + e];
    int p = atomicAdd(&g_wp[d], 1);
    g_pos[e] = p;
    g_src[p] = s;
}

__global__ void zero_stats_kernel() {
    int i = blockIdx.x * blockDim.x + threadIdx.x;
    if (i < 2 * HD) g_bnstat[i] = 0.f;
    if (i < 2 * GG) g_gstat[i] = 0.f;
}

// ---------------- TF32 tensor-core GEMM ----------------
// C[N,M] = op_A(A[N,K]) @ W[K,M] (+bias)(+add); op_A = relu(a*tS[k]+tT[k]) if tS != null.
// BM=128, BN=64, BK=16. 256 threads = 8 warps (4x2), warp tile 32x32 via mma.m16n8k8.
__device__ __forceinline__ uint32_t to_tf32(float f) {
    uint32_t r;
    asm("cvt.rna.tf32.f32 %0, %1;" : "=r"(r) : "f"(f));
    return r;
}

__device__ __forceinline__ void mma_tf32(float c[4], uint32_t a0, uint32_t a1,
                                         uint32_t a2, uint32_t a3,
                                         uint32_t b0, uint32_t b1) {
    asm volatile(
        "mma.sync.aligned.m16n8k8.row.col.f32.tf32.tf32.f32 "
        "{%0,%1,%2,%3},{%4,%5,%6,%7},{%8,%9},{%0,%1,%2,%3};"
        : "+f"(c[0]), "+f"(c[1]), "+f"(c[2]), "+f"(c[3])
        : "r"(a0), "r"(a1), "r"(a2), "r"(a3), "r"(b0), "r"(b1));
}

__global__ __launch_bounds__(256)
void gemm_kernel(const float* __restrict__ A, const float* __restrict__ W,
                 const float* __restrict__ bias, const float* __restrict__ add,
                 const float* __restrict__ tS, const float* __restrict__ tT,
                 float* __restrict__ C, int N, int K, int M) {
    constexpr int BM = 128, BN = 64, BK = 16, PAD = 20;
    __shared__ uint32_t As[BM][PAD];   // [row][k], tf32
    __shared__ uint32_t Ws[BN][PAD];   // [n][k], tf32 (transposed)

    int tid  = threadIdx.x;
    int lane = tid & 31;
    int w    = tid >> 5;
    int wr   = w >> 1;      // 0..3
    int wc   = w & 1;       // 0..1
    int lq   = lane >> 2;   // 0..7
    int lr   = lane & 3;    // 0..3

    int rowBase = blockIdx.x * BM;
    int colBase = blockIdx.y * BN;

    float acc[2][4][4];
#pragma unroll
    for (int mt = 0; mt < 2; mt++)
#pragma unroll
        for (int nt = 0; nt < 4; nt++)
#pragma unroll
            for (int i = 0; i < 4; i++) acc[mt][nt][i] = 0.f;

    // staging indices
    int arow = tid >> 1;            // 0..127
    int akq  = (tid & 1) * 8;       // 0 or 8
    int bk   = tid >> 4;            // 0..15
    int bn   = (tid & 15) * 4;      // 0..60

    for (int k0 = 0; k0 < K; k0 += BK) {
        // ---- stage A (row-major, tf32-converted, optional BN+ReLU transform) ----
        {
            int grow = rowBase + arow;
            float4 v0 = make_float4(0.f, 0.f, 0.f, 0.f);
            float4 v1 = v0;
            if (grow < N) {
                const float* ap = &A[(size_t)grow * K + k0 + akq];
                v0 = *(const float4*)ap;
                v1 = *(const float4*)(ap + 4);
                if (tS) {
                    int gk = k0 + akq;
                    float4 s0 = *(const float4*)&tS[gk];
                    float4 s1 = *(const float4*)&tS[gk + 4];
                    float4 t0 = *(const float4*)&tT[gk];
                    float4 t1 = *(const float4*)&tT[gk + 4];
                    v0.x = fmaxf(fmaf(v0.x, s0.x, t0.x), 0.f);
                    v0.y = fmaxf(fmaf(v0.y, s0.y, t0.y), 0.f);
                    v0.z = fmaxf(fmaf(v0.z, s0.z, t0.z), 0.f);
                    v0.w = fmaxf(fmaf(v0.w, s0.w, t0.w), 0.f);
                    v1.x = fmaxf(fmaf(v1.x, s1.x, t1.x), 0.f);
                    v1.y = fmaxf(fmaf(v1.y, s1.y, t1.y), 0.f);
                    v1.z = fmaxf(fmaf(v1.z, s1.z, t1.z), 0.f);
                    v1.w = fmaxf(fmaf(v1.w, s1.w, t1.w), 0.f);
                }
            }
            uint32_t* dst = &As[arow][akq];
            dst[0] = to_tf32(v0.x); dst[1] = to_tf32(v0.y);
            dst[2] = to_tf32(v0.z); dst[3] = to_tf32(v0.w);
            dst[4] = to_tf32(v1.x); dst[5] = to_tf32(v1.y);
            dst[6] = to_tf32(v1.z); dst[7] = to_tf32(v1.w);
        }
        // ---- stage W transposed ----
        {
            float4 wv = *(const float4*)&W[(size_t)(k0 + bk) * M + colBase + bn];
            Ws[bn + 0][bk] = to_tf32(wv.x);
            Ws[bn + 1][bk] = to_tf32(wv.y);
            Ws[bn + 2][bk] = to_tf32(wv.z);
            Ws[bn + 3][bk] = to_tf32(wv.w);
        }
        __syncthreads();

#pragma unroll
        for (int ks = 0; ks < 2; ks++) {
            int kb = ks * 8;
            uint32_t af[2][4];
#pragma unroll
            for (int mt = 0; mt < 2; mt++) {
                int r0 = wr * 32 + mt * 16 + lq;
                af[mt][0] = As[r0][kb + lr];
                af[mt][1] = As[r0 + 8][kb + lr];
                af[mt][2] = As[r0][kb + 4 + lr];
                af[mt][3] = As[r0 + 8][kb + 4 + lr];
            }
            uint32_t bf[4][2];
#pragma unroll
            for (int nt = 0; nt < 4; nt++) {
                int n0 = wc * 32 + nt * 8 + lq;
                bf[nt][0] = Ws[n0][kb + lr];
                bf[nt][1] = Ws[n0][kb + 4 + lr];
            }
#pragma unroll
            for (int mt = 0; mt < 2; mt++)
#pragma unroll
                for (int nt = 0; nt < 4; nt++)
                    mma_tf32(acc[mt][nt], af[mt][0], af[mt][1], af[mt][2], af[mt][3],
                             bf[nt][0], bf[nt][1]);
        }
        __syncthreads();
    }

    // ---- epilogue ----
#pragma unroll
    for (int mt = 0; mt < 2; mt++) {
#pragma unroll
        for (int nt = 0; nt < 4; nt++) {
            int c = colBase + wc * 32 + nt * 8 + 2 * lr;
            float2 bv = make_float2(0.f, 0.f);
            if (bias) bv = *(const float2*)&bias[c];
            int r0 = rowBase + wr * 32 + mt * 16 + lq;
            int r1 = r0 + 8;
            if (r0 < N) {
                float2 o = make_float2(acc[mt][nt][0] + bv.x, acc[mt][nt][1] + bv.y);
                if (add) {
                    float2 av = *(const float2*)&add[(size_t)r0 * M + c];
                    o.x += av.x; o.y += av.y;
                }
                *(float2*)&C[(size_t)r0 * M + c] = o;
            }
            if (r1 < N) {
                float2 o = make_float2(acc[mt][nt][2] + bv.x, acc[mt][nt][3] + bv.y);
                if (add) {
                    float2 av = *(const float2*)&add[(size_t)r1 * M + c];
                    o.x += av.x; o.y += av.y;
                }
                *(float2*)&C[(size_t)r1 * M + c] = o;
            }
        }
    }
}

// ---------------- fused edge kernel: e-projection GEMM + leaky + att dot ----------------
__device__ __forceinline__ float lky(float v) { return v > 0.f ? v : NEG * v; }

__global__ __launch_bounds__(256)
void edge_fused_kernel(const int* __restrict__ ei, const float* __restrict__ ea,
                       const float* __restrict__ We, const float* __restrict__ att) {
    constexpr int TE = 128;   // edges per block
    constexpr int EW = 16;    // edges per warp
    __shared__ float ea_s[TE * EDD];      // 16 KB
    __shared__ float We_s[EDD * DD];      // 16 KB
    __shared__ float att_s[DD];

    int tid  = threadIdx.x;
    int lane = tid & 31;
    int w    = tid >> 5;
    int e0   = blockIdx.x * TE;

    {
        const float4* We4 = (const float4*)We;
        float4* Ws4 = (float4*)We_s;
#pragma unroll
        for (int i = 0; i < 4; i++) Ws4[tid + 256 * i] = We4[tid + 256 * i];
        const float4* ea4 = (const float4*)(ea + (size_t)e0 * EDD);
        float4* es4 = (float4*)ea_s;
#pragma unroll
        for (int i = 0; i < 4; i++) es4[tid + 256 * i] = ea4[tid + 256 * i];
        if (tid < DD) att_s[tid] = att[tid];
    }
    __syncthreads();

    float acc[EW][4];
#pragma unroll
    for (int i = 0; i < EW; i++)
#pragma unroll
        for (int j = 0; j < 4; j++) acc[i][j] = 0.f;

#pragma unroll
    for (int k = 0; k < EDD; k++) {
        float4 wv = *(float4*)&We_s[k * DD + lane * 4];
#pragma unroll
        for (int i = 0; i < EW; i++) {
            float a = ea_s[(w * EW + i) * EDD + k];
            acc[i][0] = fmaf(a, wv.x, acc[i][0]);
            acc[i][1] = fmaf(a, wv.y, acc[i][1]);
            acc[i][2] = fmaf(a, wv.z, acc[i][2]);
            acc[i][3] = fmaf(a, wv.w, acc[i][3]);
        }
    }

    float4 attv = *(float4*)&att_s[lane * 4];

#pragma unroll 4
    for (int i = 0; i < EW; i++) {
        int e = e0 + w * EW + i;
        int s = ei[e];
        int d = ei[NE + e];
        float4 xlv = *(const float4*)&g_xl[(size_t)s * DD + lane * 4];
        float4 xrv = *(const float4*)&g_xr[(size_t)d * DD + lane * 4];
        float mx = lky(acc[i][0] + xlv.x + xrv.x);
        float my = lky(acc[i][1] + xlv.y + xrv.y);
        float mz = lky(acc[i][2] + xlv.z + xrv.z);
        float mw = lky(acc[i][3] + xlv.w + xrv.w);
        float p = mx * attv.x + my * attv.y + mz * attv.z + mw * attv.w;
        p += __shfl_xor_sync(0xffffffffu, p, 1);
        p += __shfl_xor_sync(0xffffffffu, p, 2);
        int pos = g_pos[e];
        if ((lane & 3) == 0) g_alpha[(size_t)pos * NH + (lane >> 2)] = p;
    }
}

// ---------------- node aggregation: online softmax, CSR-sequential streams ----------------
__global__ __launch_bounds__(256)
void node_agg_kernel() {
    int lane = threadIdx.x & 31;
    int n = blockIdx.x * 8 + (threadIdx.x >> 5);
    if (n >= NN) return;
    int h = lane >> 2;
    int beg = g_rowptr[n], end = g_rowptr[n + 1];
    float m = NEG_INF, den = 0.f;
    float4 acc = make_float4(0.f, 0.f, 0.f, 0.f);

    int j = beg;
    for (; j + 1 < end; j += 2) {
        float a0 = g_alpha[(size_t)j * NH + h];
        float a1 = g_alpha[(size_t)(j + 1) * NH + h];
        int   s0 = g_src[j];
        int   s1 = g_src[j + 1];
        float4 x0 = *(const float4*)&g_xl[(size_t)s0 * DD + lane * 4];
        float4 x1 = *(const float4*)&g_xl[(size_t)s1 * DD + lane * 4];

        float mn = fmaxf(m, a0);
        float corr = __expf(m - mn);
        float p = __expf(a0 - mn);
        den = den * corr + p;
        acc.x = acc.x * corr + p * x0.x;
        acc.y = acc.y * corr + p * x0.y;
        acc.z = acc.z * corr + p * x0.z;
        acc.w = acc.w * corr + p * x0.w;
        m = mn;

        mn = fmaxf(m, a1);
        corr = __expf(m - mn);
        p = __expf(a1 - mn);
        den = den * corr + p;
        acc.x = acc.x * corr + p * x1.x;
        acc.y = acc.y * corr + p * x1.y;
        acc.z = acc.z * corr + p * x1.z;
        acc.w = acc.w * corr + p * x1.w;
        m = mn;
    }
    for (; j < end; j++) {
        float a = g_alpha[(size_t)j * NH + h];
        int s = g_src[j];
        float4 xlv = *(const float4*)&g_xl[(size_t)s * DD + lane * 4];
        float mn = fmaxf(m, a);
        float corr = __expf(m - mn);
        float p = __expf(a - mn);
        den = den * corr + p;
        acc.x = acc.x * corr + p * xlv.x;
        acc.y = acc.y * corr + p * xlv.y;
        acc.z = acc.z * corr + p * xlv.z;
        acc.w = acc.w * corr + p * xlv.w;
        m = mn;
    }

    float inv = 1.f / (den + 1e-16f);
    float4 rv = *(const float4*)&g_xres[(size_t)n * DD + lane * 4];
    float4 o = make_float4(acc.x * inv + rv.x, acc.y * inv + rv.y,
                           acc.z * inv + rv.z, acc.w * inv + rv.w);
    *(float4*)&g_xtmp[(size_t)n * DD + lane * 4] = o;
}

// ---------------- BN column stats over g_h [NN, HD] ----------------
__global__ void colstats_kernel() {
    int col = blockIdx.x * 128 + threadIdx.x;
    constexpr int CHUNK = (NN + 63) / 64;  // 782
    int r0 = blockIdx.y * CHUNK;
    int r1 = min(r0 + CHUNK, NN);
    float s = 0.f, q = 0.f;
    for (int r = r0; r < r1; r++) {
        float v = g_h[(size_t)r * HD + col];
        s += v;
        q += v * v;
    }
    atomicAdd(&g_bnstat[col], s);
    atomicAdd(&g_bnstat[HD + col], q);
}

__global__ void bn_final_kernel(const float* __restrict__ gamma, const float* __restrict__ beta) {
    int c = threadIdx.x;
    if (c >= HD) return;
    float invn = 1.f / (float)NN;
    float mu  = g_bnstat[c] * invn;
    float var = g_bnstat[HD + c] * invn - mu * mu;
    float istd = rsqrtf(var + EPSC);
    float s = gamma[c] * istd;
    g_bns[c] = s;
    g_bnt[c] = beta[c] - mu * s;
}

// ---------------- graph LayerNorm stats over g_x2 ----------------
__global__ __launch_bounds__(256)
void ln_stats_kernel(const int* __restrict__ nb) {
    int lane = threadIdx.x & 31;
    int n = blockIdx.x * 8 + (threadIdx.x >> 5);
    if (n >= NN) return;
    float4 v = *(const float4*)&g_x2[(size_t)n * DD + lane * 4];
    float s = v.x + v.y + v.z + v.w;
    float q = v.x * v.x + v.y * v.y + v.z * v.z + v.w * v.w;
#pragma unroll
    for (int off = 16; off > 0; off >>= 1) {
        s += __shfl_xor_sync(0xffffffffu, s, off);
        q += __shfl_xor_sync(0xffffffffu, q, off);
    }
    if (lane == 0) {
        int g = nb[n];
        atomicAdd(&g_gstat[g], s);
        atomicAdd(&g_gstat[GG + g], q);
    }
}

__global__ void ln_final_kernel() {
    int g = threadIdx.x;
    if (g >= GG) return;
    float cnt = fmaxf((float)g_gcnt[g], 1.f);
    float denom = cnt * (float)DD;
    float mean = g_gstat[g] / denom;
    float var  = g_gstat[GG + g] / denom - mean * mean;
    g_gmean[g] = mean;
    g_ginv[g]  = rsqrtf(var + EPSC);
}

__global__ void ln_apply_kernel(const int* __restrict__ nb,
                                const float* __restrict__ gamma,
                                const float* __restrict__ beta,
                                float* __restrict__ dst) {
    int idx = blockIdx.x * blockDim.x + threadIdx.x;
    if (idx >= NN * (DD / 4)) return;
    int n  = idx >> 5;
    int c4 = (idx & 31) * 4;
    int g  = nb[n];
    float mean = g_gmean[g];
    float ginv = g_ginv[g];
    float4 v  = *(const float4*)&g_x2[(size_t)n * DD + c4];
    float4 ga = *(const float4*)&gamma[c4];
    float4 be = *(const float4*)&beta[c4];
    float4 o;
    o.x = (v.x - mean) * ginv * ga.x + be.x;
    o.y = (v.y - mean) * ginv * ga.y + be.y;
    o.z = (v.z - mean) * ginv * ga.z + be.z;
    o.w = (v.w - mean) * ginv * ga.w + be.w;
    *(float4*)&dst[(size_t)n * DD + c4] = o;
}

// ---------------- host launch ----------------
extern "C" void kernel_launch(void* const* d_in, const int* in_sizes, int n_in,
                              void* d_out, int out_size) {
    const float* x    = (const float*)d_in[0];
    const int*   nb   = (const int*)  d_in[1];
    const int*   ei   = (const int*)  d_in[2];
    const float* ea   = (const float*)d_in[3];
    const float* Wl   = (const float*)d_in[4];
    const float* bl   = (const float*)d_in[5];
    const float* Wr   = (const float*)d_in[6];
    const float* br   = (const float*)d_in[7];
    const float* We   = (const float*)d_in[8];
    const float* att  = (const float*)d_in[9];
    const float* bias = (const float*)d_in[10];
    const float* Wres = (const float*)d_in[11];
    const float* W1   = (const float*)d_in[12];
    const float* b1   = (const float*)d_in[13];
    const float* bng  = (const float*)d_in[14];
    const float* bnb  = (const float*)d_in[15];
    const float* W2   = (const float*)d_in[16];
    const float* b2   = (const float*)d_in[17];
    const float* lng  = (const float*)d_in[18];
    const float* lnb  = (const float*)d_in[19];
    float* out = (float*)d_out;

    void* p;
    cudaGetSymbolAddress(&p, g_xl);   float* pxl   = (float*)p;
    cudaGetSymbolAddress(&p, g_xr);   float* pxr   = (float*)p;
    cudaGetSymbolAddress(&p, g_xres); float* pxres = (float*)p;
    cudaGetSymbolAddress(&p, g_xtmp); float* pxtmp = (float*)p;
    cudaGetSymbolAddress(&p, g_x2);   float* px2   = (float*)p;
    cudaGetSymbolAddress(&p, g_xcur); float* pxcur = (float*)p;
    cudaGetSymbolAddress(&p, g_h);    float* ph    = (float*)p;
    cudaGetSymbolAddress(&p, g_bns);  float* pbns  = (float*)p;
    cudaGetSymbolAddress(&p, g_bnt);  float* pbnt  = (float*)p;

    // CSR build + graph counts (shared by both layers)
    zero_init_kernel<<<(NN + 255) / 256, 256>>>();
    hist_kernel<<<(NE + 255) / 256, 256>>>(ei, nb);
    scan_kernel<<<1, 1024>>>();
    scatter_kernel<<<(NE + 255) / 256, 256>>>(ei);

    const int GR = (NN + 127) / 128;   // 391

    const float* xin = x;
    for (int l = 0; l < 2; l++) {
        zero_stats_kernel<<<2, 1024>>>();

        gemm_kernel<<<dim3(GR, 2), 256>>>(xin, Wl + (size_t)l * DD * DD, bl + l * DD,
                                          nullptr, nullptr, nullptr, pxl, NN, DD, DD);
        gemm_kernel<<<dim3(GR, 2), 256>>>(xin, Wr + (size_t)l * DD * DD, br + l * DD,
                                          nullptr, nullptr, nullptr, pxr, NN, DD, DD);
        gemm_kernel<<<dim3(GR, 2), 256>>>(xin, Wres + (size_t)l * DD * DD, bias + l * DD,
                                          nullptr, nullptr, nullptr, pxres, NN, DD, DD);

        edge_fused_kernel<<<NE / 128, 256>>>(ei, ea, We + (size_t)l * EDD * DD, att + l * DD);
        node_agg_kernel<<<(NN + 7) / 8, 256>>>();

        gemm_kernel<<<dim3(GR, 8), 256>>>(pxtmp, W1 + (size_t)l * DD * HD, b1 + l * HD,
                                          nullptr, nullptr, nullptr, ph, NN, DD, HD);
        colstats_kernel<<<dim3(4, 64), 128>>>();
        bn_final_kernel<<<1, 512>>>(bng + l * HD, bnb + l * HD);
        gemm_kernel<<<dim3(GR, 2), 256>>>(ph, W2 + (size_t)l * HD * DD, b2 + l * DD,
                                          pxtmp, pbns, pbnt, px2, NN, HD, DD);

        ln_stats_kernel<<<(NN + 7) / 8, 256>>>(nb);
        ln_final_kernel<<<1, 64>>>();
        float* dst = (l == 1) ? out : pxcur;
        ln_apply_kernel<<<(NN * (DD / 4) + 255) / 256, 256>>>(nb, lng + l * DD, lnb + l * DD, dst);

        xin = pxcur;
    }
}